// round 1
// baseline (speedup 1.0000x reference)
#include <cuda_runtime.h>
#include <math_constants.h>

#define B_  8
#define N_  1024
#define C_  768
#define H_  12
#define D_  64
#define SCALE_ 0.125f

// Scratch (device globals: no allocation allowed)
__device__ float g_qkv[(size_t)B_ * N_ * 3 * C_];   // [8192][2304]
__device__ float g_attn[(size_t)B_ * N_ * C_];      // [8192][768]

// ---------------------------------------------------------------------------
// Tiled fp32 GEMM:  C[M,Nn] = A[M,K] @ W[Nn,K]^T  (+ epilogue)
// MODE 0: qkv — add scale_emb to columns [768,1536)  (extra = scale_emb[768])
// MODE 1: proj — add bias per column                  (extra = bias[Nn])
// Tile 128x128x16, 256 threads, 8x8 per thread (split 4+4 in each dim).
// ---------------------------------------------------------------------------
template <int MODE>
__global__ __launch_bounds__(256) void gemm_kernel(
    const float* __restrict__ A, const float* __restrict__ W,
    float* __restrict__ Cout, int M, int Nn, int K,
    const float* __restrict__ extra)
{
    __shared__ float As[16 * 132];
    __shared__ float Bs[16 * 132];

    const int tid = threadIdx.x;
    const int tx = tid & 15;
    const int ty = tid >> 4;
    const int m0 = blockIdx.y * 128;
    const int n0 = blockIdx.x * 128;

    float acc[8][8];
#pragma unroll
    for (int i = 0; i < 8; i++)
#pragma unroll
        for (int j = 0; j < 8; j++) acc[i][j] = 0.f;

    const int rowL = tid >> 2;     // 0..63
    const int c4   = tid & 3;      // 0..3 (float4 within 16-wide k slab)

    for (int kt = 0; kt < K; kt += 16) {
#pragma unroll
        for (int it = 0; it < 2; ++it) {
            int r = rowL + it * 64;
            float4 va = *(const float4*)(A + (size_t)(m0 + r) * K + kt + c4 * 4);
            float4 vb = *(const float4*)(W + (size_t)(n0 + r) * K + kt + c4 * 4);
            int cb = c4 * 4;
            As[(cb + 0) * 132 + r] = va.x;
            As[(cb + 1) * 132 + r] = va.y;
            As[(cb + 2) * 132 + r] = va.z;
            As[(cb + 3) * 132 + r] = va.w;
            Bs[(cb + 0) * 132 + r] = vb.x;
            Bs[(cb + 1) * 132 + r] = vb.y;
            Bs[(cb + 2) * 132 + r] = vb.z;
            Bs[(cb + 3) * 132 + r] = vb.w;
        }
        __syncthreads();

#pragma unroll
        for (int k = 0; k < 16; k++) {
            float a[8], b[8];
            *(float4*)(a)     = *(const float4*)&As[k * 132 + ty * 4];
            *(float4*)(a + 4) = *(const float4*)&As[k * 132 + 64 + ty * 4];
            *(float4*)(b)     = *(const float4*)&Bs[k * 132 + tx * 4];
            *(float4*)(b + 4) = *(const float4*)&Bs[k * 132 + 64 + tx * 4];
#pragma unroll
            for (int i = 0; i < 8; i++)
#pragma unroll
                for (int j = 0; j < 8; j++) acc[i][j] += a[i] * b[j];
        }
        __syncthreads();
    }

#pragma unroll
    for (int i = 0; i < 8; i++) {
        int r = m0 + ((i < 4) ? (ty * 4 + i) : (64 + ty * 4 + (i - 4)));
#pragma unroll
        for (int jh = 0; jh < 2; jh++) {
            int c = n0 + jh * 64 + tx * 4;
            float v[4];
#pragma unroll
            for (int u = 0; u < 4; u++) v[u] = acc[i][(jh < 1 ? 0 : 4) + u];
            if (MODE == 0) {
#pragma unroll
                for (int u = 0; u < 4; u++) {
                    int cc = c + u;
                    if (cc >= 768 && cc < 1536) v[u] += extra[cc - 768];
                }
            } else {
#pragma unroll
                for (int u = 0; u < 4; u++) v[u] += extra[c + u];
            }
            float4 o;
            o.x = v[0]; o.y = v[1]; o.z = v[2]; o.w = v[3];
            *(float4*)(Cout + (size_t)r * Nn + c) = o;
        }
    }
}

// ---------------------------------------------------------------------------
// Fused attention: per (b,h), 64 query rows per block, two passes over 16
// K-tiles of 64. Pass 1: online max/sumexp. Pass 2: recompute scores, write
// probs (if requested), P@V accumulation.
// Smem: Qs (Q^T swizzled), KP (K^T swizzled, reused as P^T swizzled), Vs.
// ---------------------------------------------------------------------------
__device__ __forceinline__ int swz(int rr, int cc) {
    // row-major 64x64 with float4-group xor swizzle keyed by rr>>2
    return (rr << 6) + ((((cc >> 2) ^ (rr >> 2)) & 15) << 2) + (cc & 3);
}

// load 64 rows x 64 cols from g (row stride ldm) transposed into buf[d][r], swizzled
__device__ __forceinline__ void load_T(float* buf, const float* g, int ldm, int tid) {
#pragma unroll
    for (int it = 0; it < 4; ++it) {
        int f4 = tid + (it << 8);
        int r = f4 >> 4;
        int d4 = f4 & 15;
        float4 v = *(const float4*)(g + (size_t)r * ldm + (d4 << 2));
        int d0 = d4 << 2;
        buf[swz(d0 + 0, r)] = v.x;
        buf[swz(d0 + 1, r)] = v.y;
        buf[swz(d0 + 2, r)] = v.z;
        buf[swz(d0 + 3, r)] = v.w;
    }
}

__global__ __launch_bounds__(256) void attn_kernel(float* __restrict__ probs)
{
    __shared__ float Qs[4096];
    __shared__ float KP[4096];   // K^T in QK phases, P^T in PV phase
    __shared__ float Vs[4096];   // V natural; overlaid by softmax reduction in pass 1

    const int tid = threadIdx.x;
    const int tx = tid & 15;
    const int ty = tid >> 4;
    const int bh = blockIdx.y;
    const int b  = bh / H_;
    const int h  = bh % H_;
    const int q0 = blockIdx.x * 64;

    const float* base = g_qkv + (size_t)b * N_ * (3 * C_);
    const float* qg = base + (size_t)q0 * (3 * C_) + h * 64;          // Q rows q0..
    const float* kg = base + 768  + h * 64;                            // K rows 0..
    const float* vg = base + 1536 + h * 64;                            // V rows 0..

    load_T(Qs, qg, 3 * C_, tid);

    float lm[4], ls[4];
#pragma unroll
    for (int i = 0; i < 4; i++) { lm[i] = -CUDART_INF_F; ls[i] = 0.f; }

    // ---------------- pass 1: online max / sumexp ----------------
    for (int t = 0; t < 16; ++t) {
        __syncthreads();
        load_T(KP, kg + (size_t)t * 64 * (3 * C_), 3 * C_, tid);
        __syncthreads();

        float s[4][4];
#pragma unroll
        for (int i = 0; i < 4; i++)
#pragma unroll
            for (int j = 0; j < 4; j++) s[i][j] = 0.f;

#pragma unroll 8
        for (int d = 0; d < 64; d++) {
            int ph = (d >> 2) & 15;
            float4 qa = *(const float4*)&Qs[(d << 6) + (((ty ^ ph) & 15) << 2)];
            float4 kb = *(const float4*)&KP[(d << 6) + (((tx ^ ph) & 15) << 2)];
            const float a[4] = {qa.x, qa.y, qa.z, qa.w};
            const float bb[4] = {kb.x, kb.y, kb.z, kb.w};
#pragma unroll
            for (int i = 0; i < 4; i++)
#pragma unroll
                for (int j = 0; j < 4; j++) s[i][j] += a[i] * bb[j];
        }
#pragma unroll
        for (int i = 0; i < 4; i++) {
#pragma unroll
            for (int j = 0; j < 4; j++) s[i][j] *= SCALE_;
            float tm = fmaxf(fmaxf(s[i][0], s[i][1]), fmaxf(s[i][2], s[i][3]));
            float nm = fmaxf(lm[i], tm);
            float add = __expf(s[i][0] - nm) + __expf(s[i][1] - nm)
                      + __expf(s[i][2] - nm) + __expf(s[i][3] - nm);
            ls[i] = ls[i] * __expf(lm[i] - nm) + add;
            lm[i] = nm;
        }
    }

    // ---------------- cross-thread softmax reduction (overlay Vs) -------------
    float* Mred = Vs;
    float* Sred = Vs + 1024;
    float* Mrow = Vs + 2048;
    float* Sinv = Vs + 2112;
    __syncthreads();
#pragma unroll
    for (int i = 0; i < 4; i++) {
        int r = ty * 4 + i;
        Mred[r * 16 + tx] = lm[i];
        Sred[r * 16 + tx] = ls[i];
    }
    __syncthreads();
    if (tid < 64) {
        float M = -CUDART_INF_F;
#pragma unroll
        for (int u = 0; u < 16; u++) M = fmaxf(M, Mred[tid * 16 + u]);
        float S = 0.f;
#pragma unroll
        for (int u = 0; u < 16; u++) S += Sred[tid * 16 + u] * __expf(Mred[tid * 16 + u] - M);
        Mrow[tid] = M;
        Sinv[tid] = 1.f / S;
    }
    __syncthreads();
    float rM[4], rI[4];
#pragma unroll
    for (int i = 0; i < 4; i++) {
        rM[i] = Mrow[ty * 4 + i];
        rI[i] = Sinv[ty * 4 + i];
    }

    // ---------------- pass 2: probs + P@V ----------------
    float o[4][4];
#pragma unroll
    for (int i = 0; i < 4; i++)
#pragma unroll
        for (int j = 0; j < 4; j++) o[i][j] = 0.f;

    for (int t = 0; t < 16; ++t) {
        __syncthreads();
        load_T(KP, kg + (size_t)t * 64 * (3 * C_), 3 * C_, tid);
        // V natural layout
#pragma unroll
        for (int it = 0; it < 4; ++it) {
            int f4 = tid + (it << 8);
            int r = f4 >> 4, d4 = f4 & 15;
            *(float4*)&Vs[(r << 6) + (d4 << 2)] =
                *(const float4*)(vg + ((size_t)t * 64 + r) * (3 * C_) + (d4 << 2));
        }
        __syncthreads();

        float s[4][4];
#pragma unroll
        for (int i = 0; i < 4; i++)
#pragma unroll
            for (int j = 0; j < 4; j++) s[i][j] = 0.f;

#pragma unroll 8
        for (int d = 0; d < 64; d++) {
            int ph = (d >> 2) & 15;
            float4 qa = *(const float4*)&Qs[(d << 6) + (((ty ^ ph) & 15) << 2)];
            float4 kb = *(const float4*)&KP[(d << 6) + (((tx ^ ph) & 15) << 2)];
            const float a[4] = {qa.x, qa.y, qa.z, qa.w};
            const float bb[4] = {kb.x, kb.y, kb.z, kb.w};
#pragma unroll
            for (int i = 0; i < 4; i++)
#pragma unroll
                for (int j = 0; j < 4; j++) s[i][j] += a[i] * bb[j];
        }

        float p[4][4];
#pragma unroll
        for (int i = 0; i < 4; i++)
#pragma unroll
            for (int j = 0; j < 4; j++)
                p[i][j] = __expf(s[i][j] * SCALE_ - rM[i]) * rI[i];

        if (probs) {
#pragma unroll
            for (int i = 0; i < 4; i++) {
                float4 v;
                v.x = p[i][0]; v.y = p[i][1]; v.z = p[i][2]; v.w = p[i][3];
                *(float4*)(probs + ((size_t)bh * N_ + q0 + ty * 4 + i) * N_
                                 + t * 64 + tx * 4) = v;
            }
        }

        __syncthreads();   // everyone done reading KP as K
#pragma unroll
        for (int i = 0; i < 4; i++)
#pragma unroll
            for (int j = 0; j < 4; j++)
                KP[swz(tx * 4 + j, ty * 4 + i)] = p[i][j];   // store P^T swizzled
        __syncthreads();

#pragma unroll 8
        for (int key = 0; key < 64; key++) {
            int ph = (key >> 2) & 15;
            float4 pa = *(const float4*)&KP[(key << 6) + (((ty ^ ph) & 15) << 2)];
            float4 vb = *(const float4*)&Vs[(key << 6) + (tx << 2)];
            const float a[4] = {pa.x, pa.y, pa.z, pa.w};
            const float bb[4] = {vb.x, vb.y, vb.z, vb.w};
#pragma unroll
            for (int i = 0; i < 4; i++)
#pragma unroll
                for (int j = 0; j < 4; j++) o[i][j] += a[i] * bb[j];
        }
    }

    // write attention output (B,N,C) layout: row b*N+q, col h*64 + d
#pragma unroll
    for (int i = 0; i < 4; i++) {
        float4 v;
        v.x = o[i][0]; v.y = o[i][1]; v.z = o[i][2]; v.w = o[i][3];
        *(float4*)(g_attn + ((size_t)b * N_ + q0 + ty * 4 + i) * C_ + h * 64 + tx * 4) = v;
    }
}

// ---------------------------------------------------------------------------
extern "C" void kernel_launch(void* const* d_in, const int* in_sizes, int n_in,
                              void* d_out, int out_size)
{
    const float* x     = (const float*)d_in[0];
    const float* se    = (const float*)d_in[1];
    const float* wqkv  = (const float*)d_in[2];
    const float* wproj = (const float*)d_in[3];
    const float* bproj = (const float*)d_in[4];

    float* out = (float*)d_out;
    const long long OUTN = (long long)B_ * N_ * C_;                 // 6,291,456
    const long long PRN  = (long long)B_ * H_ * N_ * N_;            // 100,663,296

    float* probs = nullptr;
    bool do_proj = true;
    if ((long long)out_size >= OUTN + PRN) {
        probs = out + OUTN;                 // (out, attn_probs) concatenated
    } else if ((long long)out_size == PRN) {
        probs = out;                        // probs-only output
        do_proj = false;
    }                                       // else: out-only, skip probs write

    float* qkv = nullptr;
    float* attn = nullptr;
    cudaGetSymbolAddress((void**)&qkv, g_qkv);
    cudaGetSymbolAddress((void**)&attn, g_attn);

    // 1) qkv = x @ w_qkv^T, fused +scale_emb on K slice
    {
        dim3 grid(3 * C_ / 128, (B_ * N_) / 128);   // (18, 64)
        gemm_kernel<0><<<grid, 256>>>(x, wqkv, qkv, B_ * N_, 3 * C_, C_, se);
    }
    // 2) fused attention (+ probs output)
    {
        dim3 grid(N_ / 64, B_ * H_);                // (16, 96)
        attn_kernel<<<grid, 256>>>(probs);
    }
    // 3) out = attn @ w_proj^T + b_proj
    if (do_proj) {
        dim3 grid(C_ / 128, (B_ * N_) / 128);       // (6, 64)
        gemm_kernel<1><<<grid, 256>>>(attn, wproj, out, B_ * N_, C_, C_, bproj);
    }
}

// round 2
// speedup vs baseline: 1.6318x; 1.6318x over previous
#include <cuda_runtime.h>
#include <math_constants.h>

#define B_  8
#define N_  1024
#define C_  768
#define H_  12
#define D_  64
#define SCALE_ 0.125f

// Scratch (device globals: no allocation allowed)
__device__ float g_qkv[(size_t)B_ * N_ * 3 * C_];   // [8192][2304]
__device__ float g_attn[(size_t)B_ * N_ * C_];      // [8192][768]

// ---------------------------------------------------------------------------
// Tiled fp32 GEMM:  C[M,Nn] = A[M,K] @ W[Nn,K]^T  (+ epilogue)
// MODE 0: qkv — add scale_emb to columns [768,1536)  (extra = scale_emb[768])
// MODE 1: proj — add bias per column                  (extra = bias[Nn])
// Tile 128x128x16, 256 threads, 8x8 per thread (split 4+4 in each dim).
// ---------------------------------------------------------------------------
template <int MODE>
__global__ __launch_bounds__(256) void gemm_kernel(
    const float* __restrict__ A, const float* __restrict__ W,
    float* __restrict__ Cout, int M, int Nn, int K,
    const float* __restrict__ extra)
{
    __shared__ float As[16 * 132];
    __shared__ float Bs[16 * 132];

    const int tid = threadIdx.x;
    const int tx = tid & 15;
    const int ty = tid >> 4;
    const int m0 = blockIdx.y * 128;
    const int n0 = blockIdx.x * 128;

    float acc[8][8];
#pragma unroll
    for (int i = 0; i < 8; i++)
#pragma unroll
        for (int j = 0; j < 8; j++) acc[i][j] = 0.f;

    const int rowL = tid >> 2;     // 0..63
    const int c4   = tid & 3;      // 0..3 (float4 within 16-wide k slab)

    for (int kt = 0; kt < K; kt += 16) {
#pragma unroll
        for (int it = 0; it < 2; ++it) {
            int r = rowL + it * 64;
            float4 va = *(const float4*)(A + (size_t)(m0 + r) * K + kt + c4 * 4);
            float4 vb = *(const float4*)(W + (size_t)(n0 + r) * K + kt + c4 * 4);
            int cb = c4 * 4;
            As[(cb + 0) * 132 + r] = va.x;
            As[(cb + 1) * 132 + r] = va.y;
            As[(cb + 2) * 132 + r] = va.z;
            As[(cb + 3) * 132 + r] = va.w;
            Bs[(cb + 0) * 132 + r] = vb.x;
            Bs[(cb + 1) * 132 + r] = vb.y;
            Bs[(cb + 2) * 132 + r] = vb.z;
            Bs[(cb + 3) * 132 + r] = vb.w;
        }
        __syncthreads();

#pragma unroll
        for (int k = 0; k < 16; k++) {
            float a[8], b[8];
            *(float4*)(a)     = *(const float4*)&As[k * 132 + ty * 4];
            *(float4*)(a + 4) = *(const float4*)&As[k * 132 + 64 + ty * 4];
            *(float4*)(b)     = *(const float4*)&Bs[k * 132 + tx * 4];
            *(float4*)(b + 4) = *(const float4*)&Bs[k * 132 + 64 + tx * 4];
#pragma unroll
            for (int i = 0; i < 8; i++)
#pragma unroll
                for (int j = 0; j < 8; j++) acc[i][j] += a[i] * b[j];
        }
        __syncthreads();
    }

#pragma unroll
    for (int i = 0; i < 8; i++) {
        int r = m0 + ((i < 4) ? (ty * 4 + i) : (64 + ty * 4 + (i - 4)));
#pragma unroll
        for (int jh = 0; jh < 2; jh++) {
            int c = n0 + jh * 64 + tx * 4;
            float v[4];
#pragma unroll
            for (int u = 0; u < 4; u++) v[u] = acc[i][(jh < 1 ? 0 : 4) + u];
            if (MODE == 0) {
#pragma unroll
                for (int u = 0; u < 4; u++) {
                    int cc = c + u;
                    if (cc >= 768 && cc < 1536) v[u] += extra[cc - 768];
                }
            } else {
#pragma unroll
                for (int u = 0; u < 4; u++) v[u] += extra[c + u];
            }
            float4 o;
            o.x = v[0]; o.y = v[1]; o.z = v[2]; o.w = v[3];
            *(float4*)(Cout + (size_t)r * Nn + c) = o;
        }
    }
}

// ---------------------------------------------------------------------------
// Fused attention: per (b,h), 64 query rows per block, two passes over 16
// K-tiles of 64. Pass 1: online max/sumexp. Pass 2: recompute scores, write
// probs (if requested), P@V accumulation.
// Smem: Qs (Q^T swizzled), KP (K^T swizzled, reused as P^T swizzled), Vs.
// ---------------------------------------------------------------------------
__device__ __forceinline__ int swz(int rr, int cc) {
    // row-major 64x64 with float4-group xor swizzle keyed by rr>>2
    return (rr << 6) + ((((cc >> 2) ^ (rr >> 2)) & 15) << 2) + (cc & 3);
}

// load 64 rows x 64 cols from g (row stride ldm) transposed into buf[d][r], swizzled
__device__ __forceinline__ void load_T(float* buf, const float* g, int ldm, int tid) {
#pragma unroll
    for (int it = 0; it < 4; ++it) {
        int f4 = tid + (it << 8);
        int r = f4 >> 4;
        int d4 = f4 & 15;
        float4 v = *(const float4*)(g + (size_t)r * ldm + (d4 << 2));
        int d0 = d4 << 2;
        buf[swz(d0 + 0, r)] = v.x;
        buf[swz(d0 + 1, r)] = v.y;
        buf[swz(d0 + 2, r)] = v.z;
        buf[swz(d0 + 3, r)] = v.w;
    }
}

__global__ __launch_bounds__(256) void attn_kernel(float* __restrict__ probs)
{
    __shared__ float Qs[4096];
    __shared__ float KP[4096];   // K^T in QK phases, P^T in PV phase
    __shared__ float Vs[4096];   // V natural; overlaid by softmax reduction in pass 1

    const int tid = threadIdx.x;
    const int tx = tid & 15;
    const int ty = tid >> 4;
    const int bh = blockIdx.y;
    const int b  = bh / H_;
    const int h  = bh % H_;
    const int q0 = blockIdx.x * 64;

    const float* base = g_qkv + (size_t)b * N_ * (3 * C_);
    const float* qg = base + (size_t)q0 * (3 * C_) + h * 64;          // Q rows q0..
    const float* kg = base + 768  + h * 64;                            // K rows 0..
    const float* vg = base + 1536 + h * 64;                            // V rows 0..

    load_T(Qs, qg, 3 * C_, tid);

    float lm[4], ls[4];
#pragma unroll
    for (int i = 0; i < 4; i++) { lm[i] = -CUDART_INF_F; ls[i] = 0.f; }

    // ---------------- pass 1: online max / sumexp ----------------
    for (int t = 0; t < 16; ++t) {
        __syncthreads();
        load_T(KP, kg + (size_t)t * 64 * (3 * C_), 3 * C_, tid);
        __syncthreads();

        float s[4][4];
#pragma unroll
        for (int i = 0; i < 4; i++)
#pragma unroll
            for (int j = 0; j < 4; j++) s[i][j] = 0.f;

#pragma unroll 8
        for (int d = 0; d < 64; d++) {
            int ph = (d >> 2) & 15;
            float4 qa = *(const float4*)&Qs[(d << 6) + (((ty ^ ph) & 15) << 2)];
            float4 kb = *(const float4*)&KP[(d << 6) + (((tx ^ ph) & 15) << 2)];
            const float a[4] = {qa.x, qa.y, qa.z, qa.w};
            const float bb[4] = {kb.x, kb.y, kb.z, kb.w};
#pragma unroll
            for (int i = 0; i < 4; i++)
#pragma unroll
                for (int j = 0; j < 4; j++) s[i][j] += a[i] * bb[j];
        }
#pragma unroll
        for (int i = 0; i < 4; i++) {
#pragma unroll
            for (int j = 0; j < 4; j++) s[i][j] *= SCALE_;
            float tm = fmaxf(fmaxf(s[i][0], s[i][1]), fmaxf(s[i][2], s[i][3]));
            float nm = fmaxf(lm[i], tm);
            float add = __expf(s[i][0] - nm) + __expf(s[i][1] - nm)
                      + __expf(s[i][2] - nm) + __expf(s[i][3] - nm);
            ls[i] = ls[i] * __expf(lm[i] - nm) + add;
            lm[i] = nm;
        }
    }

    // ---------------- cross-thread softmax reduction (overlay Vs) -------------
    float* Mred = Vs;
    float* Sred = Vs + 1024;
    float* Mrow = Vs + 2048;
    float* Sinv = Vs + 2112;
    __syncthreads();
#pragma unroll
    for (int i = 0; i < 4; i++) {
        int r = ty * 4 + i;
        Mred[r * 16 + tx] = lm[i];
        Sred[r * 16 + tx] = ls[i];
    }
    __syncthreads();
    if (tid < 64) {
        float M = -CUDART_INF_F;
#pragma unroll
        for (int u = 0; u < 16; u++) M = fmaxf(M, Mred[tid * 16 + u]);
        float S = 0.f;
#pragma unroll
        for (int u = 0; u < 16; u++) S += Sred[tid * 16 + u] * __expf(Mred[tid * 16 + u] - M);
        Mrow[tid] = M;
        Sinv[tid] = 1.f / S;
    }
    __syncthreads();
    float rM[4], rI[4];
#pragma unroll
    for (int i = 0; i < 4; i++) {
        rM[i] = Mrow[ty * 4 + i];
        rI[i] = Sinv[ty * 4 + i];
    }

    // ---------------- pass 2: probs + P@V ----------------
    float o[4][4];
#pragma unroll
    for (int i = 0; i < 4; i++)
#pragma unroll
        for (int j = 0; j < 4; j++) o[i][j] = 0.f;

    for (int t = 0; t < 16; ++t) {
        __syncthreads();
        load_T(KP, kg + (size_t)t * 64 * (3 * C_), 3 * C_, tid);
        // V natural layout
#pragma unroll
        for (int it = 0; it < 4; ++it) {
            int f4 = tid + (it << 8);
            int r = f4 >> 4, d4 = f4 & 15;
            *(float4*)&Vs[(r << 6) + (d4 << 2)] =
                *(const float4*)(vg + ((size_t)t * 64 + r) * (3 * C_) + (d4 << 2));
        }
        __syncthreads();

        float s[4][4];
#pragma unroll
        for (int i = 0; i < 4; i++)
#pragma unroll
            for (int j = 0; j < 4; j++) s[i][j] = 0.f;

#pragma unroll 8
        for (int d = 0; d < 64; d++) {
            int ph = (d >> 2) & 15;
            float4 qa = *(const float4*)&Qs[(d << 6) + (((ty ^ ph) & 15) << 2)];
            float4 kb = *(const float4*)&KP[(d << 6) + (((tx ^ ph) & 15) << 2)];
            const float a[4] = {qa.x, qa.y, qa.z, qa.w};
            const float bb[4] = {kb.x, kb.y, kb.z, kb.w};
#pragma unroll
            for (int i = 0; i < 4; i++)
#pragma unroll
                for (int j = 0; j < 4; j++) s[i][j] += a[i] * bb[j];
        }

        float p[4][4];
#pragma unroll
        for (int i = 0; i < 4; i++)
#pragma unroll
            for (int j = 0; j < 4; j++)
                p[i][j] = __expf(s[i][j] * SCALE_ - rM[i]) * rI[i];

        if (probs) {
#pragma unroll
            for (int i = 0; i < 4; i++) {
                float4 v;
                v.x = p[i][0]; v.y = p[i][1]; v.z = p[i][2]; v.w = p[i][3];
                *(float4*)(probs + ((size_t)bh * N_ + q0 + ty * 4 + i) * N_
                                 + t * 64 + tx * 4) = v;
            }
        }

        __syncthreads();   // everyone done reading KP as K
#pragma unroll
        for (int i = 0; i < 4; i++)
#pragma unroll
            for (int j = 0; j < 4; j++)
                KP[swz(tx * 4 + j, ty * 4 + i)] = p[i][j];   // store P^T swizzled
        __syncthreads();

#pragma unroll 8
        for (int key = 0; key < 64; key++) {
            int ph = (key >> 2) & 15;
            float4 pa = *(const float4*)&KP[(key << 6) + (((ty ^ ph) & 15) << 2)];
            float4 vb = *(const float4*)&Vs[(key << 6) + (tx << 2)];
            const float a[4] = {pa.x, pa.y, pa.z, pa.w};
            const float bb[4] = {vb.x, vb.y, vb.z, vb.w};
#pragma unroll
            for (int i = 0; i < 4; i++)
#pragma unroll
                for (int j = 0; j < 4; j++) o[i][j] += a[i] * bb[j];
        }
    }

    // write attention output (B,N,C) layout: row b*N+q, col h*64 + d
#pragma unroll
    for (int i = 0; i < 4; i++) {
        float4 v;
        v.x = o[i][0]; v.y = o[i][1]; v.z = o[i][2]; v.w = o[i][3];
        *(float4*)(g_attn + ((size_t)b * N_ + q0 + ty * 4 + i) * C_ + h * 64 + tx * 4) = v;
    }
}

// ---------------------------------------------------------------------------
extern "C" void kernel_launch(void* const* d_in, const int* in_sizes, int n_in,
                              void* d_out, int out_size)
{
    const float* x     = (const float*)d_in[0];
    const float* se    = (const float*)d_in[1];
    const float* wqkv  = (const float*)d_in[2];
    const float* wproj = (const float*)d_in[3];
    const float* bproj = (const float*)d_in[4];

    float* out = (float*)d_out;
    const long long OUTN = (long long)B_ * N_ * C_;                 // 6,291,456
    const long long PRN  = (long long)B_ * H_ * N_ * N_;            // 100,663,296

    float* probs = nullptr;
    bool do_proj = true;
    if ((long long)out_size >= OUTN + PRN) {
        probs = out + OUTN;                 // (out, attn_probs) concatenated
    } else if ((long long)out_size == PRN) {
        probs = out;                        // probs-only output
        do_proj = false;
    }                                       // else: out-only, skip probs write

    float* qkv = nullptr;
    float* attn = nullptr;
    cudaGetSymbolAddress((void**)&qkv, g_qkv);
    cudaGetSymbolAddress((void**)&attn, g_attn);

    // 1) qkv = x @ w_qkv^T, fused +scale_emb on K slice
    {
        dim3 grid(3 * C_ / 128, (B_ * N_) / 128);   // (18, 64)
        gemm_kernel<0><<<grid, 256>>>(x, wqkv, qkv, B_ * N_, 3 * C_, C_, se);
    }
    // 2) fused attention (+ probs output)
    {
        dim3 grid(N_ / 64, B_ * H_);                // (16, 96)
        attn_kernel<<<grid, 256>>>(probs);
    }
    // 3) out = attn @ w_proj^T + b_proj
    if (do_proj) {
        dim3 grid(C_ / 128, (B_ * N_) / 128);       // (6, 64)
        gemm_kernel<1><<<grid, 256>>>(attn, wproj, out, B_ * N_, C_, C_, bproj);
    }
}